// round 3
// baseline (speedup 1.0000x reference)
#include <cuda_runtime.h>
#include <math.h>

#define T_SEQ 8192
#define HID   1024
#define GDIM  2048          // 2*H
#define NCTA  128
#define RECT  512           // 16 warps: 8 forget rows + 8 candidate rows per CTA

// ---------------- scratch (static __device__, no allocation) ----------------
__device__ float g_gi[T_SEQ * GDIM];                    // input projection (64 MB)
__device__ float g_Xa[T_SEQ * HID];                     // layer output ping
__device__ float g_Xb[T_SEQ * HID];                     // layer output pong
__device__ __align__(128) unsigned long long g_ht[2][HID];  // tagged hidden state

// ---------------- tagged-word helpers ----------------
__device__ __forceinline__ void poll2(const unsigned long long* p, unsigned tag,
                                      float& v0f, float& v1f) {
    unsigned v0, t0, v1, t1;
    do {
        asm volatile("ld.volatile.global.v4.b32 {%0,%1,%2,%3}, [%4];"
                     : "=r"(v0), "=r"(t0), "=r"(v1), "=r"(t1) : "l"(p));
    } while (t0 != tag || t1 != tag);
    v0f = __uint_as_float(v0);
    v1f = __uint_as_float(v1);
}
__device__ __forceinline__ void st_tagged(unsigned long long* p, float v, unsigned tag) {
    unsigned long long pk = ((unsigned long long)tag << 32) |
                            (unsigned long long)__float_as_uint(v);
    asm volatile("st.global.relaxed.gpu.b64 [%0], %1;" :: "l"(p), "l"(pk) : "memory");
}

// ---------------- per-layer init: seed tagged h ----------------
__global__ void init_phase(const float* __restrict__ h0, int layer) {
    int tid = blockIdx.x * blockDim.x + threadIdx.x;
    if (tid < HID) {
        unsigned long long pk = (unsigned long long)__float_as_uint(h0[layer * HID + tid]);
        g_ht[0][tid] = pk;                       // tag 0, value h0
        g_ht[1][tid] = 0xFFFFFFFF00000000ull;    // invalid tag
    }
}

// ---------------- C[M,N] = A[M,K] @ W[N,K]^T + bias[N] ----------------
__global__ __launch_bounds__(256, 2)
void gemm_bias_nt(const float* __restrict__ A, const float* __restrict__ W,
                  const float* __restrict__ bias, float* __restrict__ C,
                  int M, int N, int K) {
    __shared__ float As[8][128];
    __shared__ float Bs[8][128];
    const int tid  = threadIdx.x;
    const int bm   = blockIdx.y * 128;
    const int bn   = blockIdx.x * 128;
    const int lrow = tid >> 1;
    const int lcol = (tid & 1) << 2;
    const int ty   = tid >> 4;
    const int tx   = tid & 15;

    float acc[8][8];
#pragma unroll
    for (int i = 0; i < 8; ++i)
#pragma unroll
        for (int j = 0; j < 8; ++j) acc[i][j] = 0.f;

    const float* Aptr = A + (size_t)(bm + lrow) * K + lcol;
    const float* Wptr = W + (size_t)(bn + lrow) * K + lcol;

    for (int k0 = 0; k0 < K; k0 += 8) {
        float4 av = *(const float4*)(Aptr + k0);
        float4 wv = *(const float4*)(Wptr + k0);
        As[lcol + 0][lrow] = av.x; As[lcol + 1][lrow] = av.y;
        As[lcol + 2][lrow] = av.z; As[lcol + 3][lrow] = av.w;
        Bs[lcol + 0][lrow] = wv.x; Bs[lcol + 1][lrow] = wv.y;
        Bs[lcol + 2][lrow] = wv.z; Bs[lcol + 3][lrow] = wv.w;
        __syncthreads();
#pragma unroll
        for (int k = 0; k < 8; ++k) {
            float4 a0 = *(const float4*)&As[k][ty * 8];
            float4 a1 = *(const float4*)&As[k][ty * 8 + 4];
            float4 b0 = *(const float4*)&Bs[k][tx * 8];
            float4 b1 = *(const float4*)&Bs[k][tx * 8 + 4];
            float ar[8] = {a0.x, a0.y, a0.z, a0.w, a1.x, a1.y, a1.z, a1.w};
            float br[8] = {b0.x, b0.y, b0.z, b0.w, b1.x, b1.y, b1.z, b1.w};
#pragma unroll
            for (int i = 0; i < 8; ++i)
#pragma unroll
                for (int j = 0; j < 8; ++j) acc[i][j] += ar[i] * br[j];
        }
        __syncthreads();
    }

#pragma unroll
    for (int i = 0; i < 8; ++i) {
        int row = bm + ty * 8 + i;
#pragma unroll
        for (int j = 0; j < 8; j += 4) {
            float4 v;
            int col = bn + tx * 8 + j;
            v.x = acc[i][j + 0] + bias[col + 0];
            v.y = acc[i][j + 1] + bias[col + 1];
            v.z = acc[i][j + 2] + bias[col + 2];
            v.w = acc[i][j + 3] + bias[col + 3];
            *(float4*)&C[(size_t)row * N + col] = v;
        }
    }
}

// ---------------- persistent MGU recurrence, flag-in-data sync ----------------
// 128 CTAs x 512 threads. CTA c owns outputs j in [c*8, c*8+8).
// Warp w<8: forget row j=c*8+w. Warp w>=8: candidate row 1024+c*8+(w-8).
__global__ __launch_bounds__(RECT, 1)
void mgu_recur(const float* __restrict__ w_hh, const float* __restrict__ b_hh,
               const float* __restrict__ gi, float* __restrict__ X) {
    __shared__ __align__(16) float h_s[2][HID];   // double-buffered h stage
    __shared__ float d_n[8];                      // candidate dots (accn + b_n)

    const int cta  = blockIdx.x;
    const int tid  = threadIdx.x;
    const int warp = tid >> 5;
    const int lane = tid & 31;
    const bool isF = warp < 8;
    const int  out = cta * 8 + (warp & 7);        // output index this warp serves
    const int  row = isF ? out : HID + out;       // matrix row this warp computes

    // weights for this row: 32 floats/lane, indices 4*(i*32+lane)
    float4 wr[8];
#pragma unroll
    for (int i = 0; i < 8; ++i)
        wr[i] = *(const float4*)&w_hh[(size_t)row * HID + 4 * (i * 32 + lane)];
    const float brow = b_hh[row];

    for (int t = 0; t < T_SEQ; ++t) {
        const int p = t & 1;

        // prefetch gi (forget warps' lane 0) — independent of the poll
        float gif = 0.f, gin = 0.f;
        if (isF && lane == 0) {
            gif = __ldcg(&gi[(size_t)t * GDIM + out]);
            gin = __ldcg(&gi[(size_t)t * GDIM + HID + out]);
        }

        // poll own 2 tagged words until fresh, stage into shared
        float v0, v1;
        poll2(&g_ht[p][2 * tid], (unsigned)t, v0, v1);
        h_s[p][2 * tid]     = v0;
        h_s[p][2 * tid + 1] = v1;
        __syncthreads();

        // 1024-length dot, weights in registers, h from shared
        float a0 = 0.f, a1 = 0.f;
#pragma unroll
        for (int i = 0; i < 8; i += 2) {
            float4 ha = *(const float4*)&h_s[p][4 * (i * 32 + lane)];
            float4 hb = *(const float4*)&h_s[p][4 * ((i + 1) * 32 + lane)];
            a0 += wr[i].x * ha.x + wr[i].y * ha.y + wr[i].z * ha.z + wr[i].w * ha.w;
            a1 += wr[i+1].x * hb.x + wr[i+1].y * hb.y + wr[i+1].z * hb.z + wr[i+1].w * hb.w;
        }
        float acc = a0 + a1;
#pragma unroll
        for (int off = 16; off; off >>= 1)
            acc += __shfl_down_sync(0xffffffffu, acc, off);

        if (!isF && lane == 0) d_n[warp - 8] = acc + brow;   // candidate: h_n dot
        __syncthreads();

        if (isF && lane == 0) {
            float hn = d_n[warp & 7];
            // f = sigmoid(gi_f + acc + b_f), clamped for __expf safety
            float zf = gif + acc + brow;
            zf = fminf(fmaxf(zf, -30.f), 30.f);
            float f  = __fdividef(1.f, 1.f + __expf(-zf));
            // n = tanh(gi_n + f*hn)
            float z  = gin + f * hn;
            z = fminf(fmaxf(z, -15.f), 15.f);
            float e  = __expf(2.f * z);
            float n  = 1.f - __fdividef(2.f, e + 1.f);
            float hprev = h_s[p][out];
            float hy = n + (1.f - f) * (hprev - n);
            st_tagged(&g_ht[p ^ 1][out], hy, (unsigned)(t + 1));  // publish h(t+1)
            X[(size_t)t * HID + out] = hy;                        // fire-and-forget
        }
        // no further sync needed: d_n reuse is gated by next step's __syncthreads,
        // h_s is double-buffered.
    }
}

// ---------------- final projection: out[t] = X[t] . w_out + b_out ----------------
__global__ void out_proj(const float* __restrict__ X, const float* __restrict__ w_out,
                         const float* __restrict__ b_out, float* __restrict__ out) {
    int gwarp = (blockIdx.x * blockDim.x + threadIdx.x) >> 5;
    int lane  = threadIdx.x & 31;
    if (gwarp >= T_SEQ) return;
    float acc = 0.f;
#pragma unroll
    for (int i = 0; i < HID / 32; ++i)
        acc += X[(size_t)gwarp * HID + i * 32 + lane] * w_out[i * 32 + lane];
#pragma unroll
    for (int off = 16; off; off >>= 1) acc += __shfl_down_sync(0xffffffffu, acc, off);
    if (lane == 0) out[gwarp] = acc + b_out[0];
}

// ---------------- host launcher ----------------
extern "C" void kernel_launch(void* const* d_in, const int* in_sizes, int n_in,
                              void* d_out, int out_size) {
    const float* S         = (const float*)d_in[0];
    const float* h0        = (const float*)d_in[1];
    const float* w_ih0     = (const float*)d_in[2];
    const float* w_hh0     = (const float*)d_in[3];
    const float* b_ih0     = (const float*)d_in[4];
    const float* b_hh0     = (const float*)d_in[5];
    const float* w_ih_rest = (const float*)d_in[6];
    const float* w_hh_rest = (const float*)d_in[7];
    const float* b_ih_rest = (const float*)d_in[8];
    const float* b_hh_rest = (const float*)d_in[9];
    const float* w_out     = (const float*)d_in[10];
    const float* b_out     = (const float*)d_in[11];
    float* out             = (float*)d_out;

    float *gi, *Xa, *Xb;
    cudaGetSymbolAddress((void**)&gi, g_gi);
    cudaGetSymbolAddress((void**)&Xa, g_Xa);
    cudaGetSymbolAddress((void**)&Xb, g_Xb);

    dim3 ggrid(GDIM / 128, T_SEQ / 128);

    // ---- layer 0 ----
    gemm_bias_nt<<<ggrid, 256>>>(S, w_ih0, b_ih0, gi, T_SEQ, GDIM, 128);
    init_phase<<<1, 1024>>>(h0, 0);
    mgu_recur<<<NCTA, RECT>>>(w_hh0, b_hh0, gi, Xa);

    // ---- layer 1 ----
    gemm_bias_nt<<<ggrid, 256>>>(Xa, w_ih_rest, b_ih_rest, gi, T_SEQ, GDIM, HID);
    init_phase<<<1, 1024>>>(h0, 1);
    mgu_recur<<<NCTA, RECT>>>(w_hh_rest, b_hh_rest, gi, Xb);

    // ---- layer 2 ----
    gemm_bias_nt<<<ggrid, 256>>>(Xb, w_ih_rest + (size_t)GDIM * HID,
                                 b_ih_rest + GDIM, gi, T_SEQ, GDIM, HID);
    init_phase<<<1, 1024>>>(h0, 2);
    mgu_recur<<<NCTA, RECT>>>(w_hh_rest + (size_t)GDIM * HID,
                              b_hh_rest + GDIM, gi, Xa);

    // ---- output projection ----
    out_proj<<<T_SEQ * 32 / 256, 256>>>(Xa, w_out, b_out, out);
}